// round 16
// baseline (speedup 1.0000x reference)
#include <cuda_runtime.h>
#include <cuda_fp16.h>
#include <cstdint>

#define NV 8000
#define NVT 20000
#define C_TOTAL 960
// Kpad multiples of 64: {3136, 832, 256, 64}
#define KPAD_SUM 4288
#define A_ELEMS 3244032   // 512*3136 + 1024*832 + 2048*256 + 4096*64

// ---------------- scratch (__device__ globals; allocation-free rule) ----------------
__device__ __align__(16) __half g_a[A_ELEMS];                    // fp16 fmap [M, Kpad]
__device__ __align__(16) __half g_b[(size_t)KPAD_SUM * NV];      // [Kpad, 8000] v-major fp16
__device__ __align__(16) float g_wsel[(size_t)C_TOTAL * NV];
__device__ int g_ctr[2];

// ---------------- grid layout ----------------
#define KPG 8
#define P0_GB 12544                       // 392 p-groups x 32 v-blocks (layer 0)
#define P0_SP 1568                        // 1605632 / 1024
#define P0_GW 500                         // 64*8000 / 1024
#define P0_CNT (P0_GB + P0_SP + P0_GW)    // 14612
#define G0_END (P0_CNT + 252)             // 14864
#define P1_GB 4608                        // 144 p-groups x 32 (layers 1-3)
#define P1_SP 1600                        // (A_ELEMS - 1605632) / 1024
#define P1_GW 7000                        // 896*8000 / 1024
#define P1_CNT (P1_GB + P1_SP + P1_GW)    // 13208
#define P1_END (G0_END + P1_CNT)          // 28072
#define GRID_TOTAL (P1_END + 3528)        // 31600

__global__ void zero_ctr() { g_ctr[0] = 0; g_ctr[1] = 0; }

// ---------------- roi dtype detect (int64 vs int32; values < 20000) ----------------
__device__ __forceinline__ bool roi_is64(const int* __restrict__ r32) {
    int acc = 0;
#pragma unroll
    for (int i = 1; i < 32; i += 2) acc |= r32[i];
    return acc == 0;
}

// ---------------- GEMM helpers ----------------
#define STAGE_BYTES 32768
#define A_OFF 0          // 128 rows x 128B
#define B_OFF 16384      // 64 rows x 256B
#define SMEM_TOTAL (3 * STAGE_BYTES)   // 96 KB

__device__ __forceinline__ uint32_t smem_u32(const void* p) {
    uint32_t a;
    asm("{ .reg .u64 t; cvta.to.shared.u64 t, %1; cvt.u32.u64 %0, t; }" : "=r"(a) : "l"(p));
    return a;
}
__device__ __forceinline__ uint32_t swzA(uint32_t base, int row, int chunk) {
    return base + (uint32_t)(row * 128 + (chunk ^ (row & 7)) * 16);
}
__device__ __forceinline__ uint32_t swzB(uint32_t base, int row, int chunk) {
    return base + (uint32_t)(row * 256 + (chunk ^ (row & 7)) * 16);
}
__device__ __forceinline__ void cp16(uint32_t dst, const void* src, bool v) {
    asm volatile("cp.async.cg.shared.global [%0], [%1], 16, %2;"
                 :: "r"(dst), "l"(src), "r"(v ? 16 : 0));
}
#define CP_COMMIT() asm volatile("cp.async.commit_group;" ::: "memory")
#define CP_WAIT1()  asm volatile("cp.async.wait_group 1;" ::: "memory")

#define LDSM4(r0, r1, r2, r3, a) \
    asm volatile("ldmatrix.sync.aligned.m8n8.x4.shared.b16 {%0,%1,%2,%3}, [%4];" \
                 : "=r"(r0), "=r"(r1), "=r"(r2), "=r"(r3) : "r"(a))
#define LDSM4T(r0, r1, r2, r3, a) \
    asm volatile("ldmatrix.sync.aligned.m8n8.x4.trans.shared.b16 {%0,%1,%2,%3}, [%4];" \
                 : "=r"(r0), "=r"(r1), "=r"(r2), "=r"(r3) : "r"(a))

#define MMA(d, a, b0_, b1_) \
    asm volatile("mma.sync.aligned.m16n8k16.row.col.f32.f16.f16.f32 " \
                 "{%0,%1,%2,%3}, {%4,%5,%6,%7}, {%8,%9}, {%0,%1,%2,%3};" \
                 : "+f"((d)[0]), "+f"((d)[1]), "+f"((d)[2]), "+f"((d)[3]) \
                 : "r"((a)[0]), "r"((a)[1]), "r"((a)[2]), "r"((a)[3]), "r"(b0_), "r"(b1_))

// ---------------- prep roles (device functions) ----------------
__device__ void role_gather_b(const float* rf, int K, int kp0, size_t bOff,
                              int vb, int tid, const int* __restrict__ roi) {
    const int v = vb * 256 + tid;
    if (v < NV) {
        const bool is64 = roi_is64(roi);
        const int ri = is64 ? roi[2 * v] : roi[v];
        const float* col = rf + ri;
        float x[KPG];
#pragma unroll
        for (int i = 0; i < KPG; i++) {
            int kp = kp0 + i;
            x[i] = (kp < K) ? __ldg(col + (size_t)kp * NVT) : 0.0f;
        }
#pragma unroll
        for (int i = 0; i < KPG; i++) {
            float a = x[i];
            a = (a > 0.0f) ? a : 0.01f * a;
            g_b[bOff + (size_t)(kp0 + i) * NV + v] = __float2half_rn(a);
        }
    }
}

__device__ void role_split(int idx0, const float* __restrict__ f0, const float* __restrict__ f1,
                           const float* __restrict__ f2, const float* __restrict__ f3) {
#pragma unroll
    for (int e = 0; e < 4; e++) {
        int idx = idx0 + e;
        const float* f; int K, Kpad, base;
        if (idx < 1605632)      { f = f0; K = 3136; Kpad = 3136; base = 0; }
        else if (idx < 2457600) { f = f1; K = 784;  Kpad = 832;  base = 1605632; }
        else if (idx < 2981888) { f = f2; K = 196;  Kpad = 256;  base = 2457600; }
        else                    { f = f3; K = 49;   Kpad = 64;   base = 2981888; }
        int local = idx - base;
        int m = local / Kpad, k = local - m * Kpad;
        float x = (k < K) ? f[(size_t)m * K + k] : 0.0f;
        g_a[idx] = __float2half_rn(x);
    }
}

__device__ void role_gather_w(long long idx0, const float* __restrict__ w0,
                              const float* __restrict__ w1, const float* __restrict__ w2,
                              const float* __restrict__ w3, const int* __restrict__ roi) {
    const bool is64 = roi_is64(roi);
#pragma unroll
    for (int e = 0; e < 4; e++) {
        long long idx = idx0 + e;
        int v = (int)(idx % NV);
        int c = (int)(idx / NV);
        const float* w; int lc;
        if (c < 64)       { w = w0; lc = c; }
        else if (c < 192) { w = w1; lc = c - 64; }
        else if (c < 448) { w = w2; lc = c - 192; }
        else              { w = w3; lc = c - 448; }
        int ri = is64 ? roi[2 * v] : roi[v];
        g_wsel[(size_t)c * NV + v] = w[(size_t)lc * NVT + (size_t)ri];
    }
}

// ---------------- the mega kernel ----------------
__global__ void __launch_bounds__(256, 2)
mega(float* __restrict__ out,
     const float* __restrict__ r0, const float* __restrict__ r1,
     const float* __restrict__ r2, const float* __restrict__ r3,
     const float* __restrict__ f0, const float* __restrict__ f1,
     const float* __restrict__ f2, const float* __restrict__ f3,
     const float* __restrict__ w0, const float* __restrict__ w1,
     const float* __restrict__ w2, const float* __restrict__ w3,
     const int* __restrict__ roi)
{
    const int bid = blockIdx.x;
    const int tid = threadIdx.x;

    const bool isG0 = (bid >= P0_CNT && bid < G0_END);
    const bool isG1 = (bid >= P1_END);

    if (!isG0 && !isG1) {
        // ======== PREP roles ========
        int seg;
        if (bid < P0_CNT) {
            seg = 0;
            if (bid < P0_GB) {
                int g = bid >> 5;
                role_gather_b(r0, 3136, g * KPG, 0, bid & 31, tid, roi);
            } else if (bid < P0_GB + P0_SP) {
                role_split((bid - P0_GB) * 1024 + tid * 4, f0, f1, f2, f3);
            } else {
                role_gather_w((long long)(bid - P0_GB - P0_SP) * 1024 + tid * 4,
                              w0, w1, w2, w3, roi);
            }
        } else {
            seg = 1;
            int b2 = bid - G0_END;
            if (b2 < P1_GB) {
                int g = b2 >> 5;
                const float* rf; int K, kp0; size_t bOff;
                if (g < 104)      { rf = r1; K = 784; bOff = 25088000; kp0 = g * KPG; }
                else if (g < 136) { rf = r2; K = 196; bOff = 31744000; kp0 = (g - 104) * KPG; }
                else              { rf = r3; K = 49;  bOff = 33792000; kp0 = (g - 136) * KPG; }
                role_gather_b(rf, K, kp0, bOff, b2 & 31, tid, roi);
            } else if (b2 < P1_GB + P1_SP) {
                role_split(1605632 + (b2 - P1_GB) * 1024 + tid * 4, f0, f1, f2, f3);
            } else {
                role_gather_w(512000LL + (long long)(b2 - P1_GB - P1_SP) * 1024 + tid * 4,
                              w0, w1, w2, w3, roi);
            }
        }
        __syncthreads();
        if (tid == 0) {
            __threadfence();
            atomicAdd(&g_ctr[seg], 1);
        }
        return;
    }

    // ======== GEMM role ========
    // Wait for the prep segment this tile depends on.
    if (tid == 0) {
        int* c = isG0 ? &g_ctr[0] : &g_ctr[1];
        const int tgt = isG0 ? P0_CNT : P1_CNT;
        int v;
        do {
            asm volatile("ld.acquire.gpu.global.b32 %0, [%1];" : "=r"(v) : "l"(c));
            if (v < tgt) __nanosleep(1000);
        } while (v < tgt);
    }
    __syncthreads();

    extern __shared__ char smem[];
    const uint32_t sb = smem_u32(smem);
    const int lane = tid & 31;
    const int w = tid >> 5;
    const int wm = w >> 1;          // 0..3 (m)
    const int wn = w & 1;           // 0..1 (n)

    const int t = isG0 ? (bid - P0_CNT) : (bid - P1_END + 252);
    int Kpad, cShift, cOff, mtiles, base; size_t aOff, bOff;
    if (t < 252)       { base = 0;    mtiles = 4;  Kpad = 3136; aOff = 0;       bOff = 0;        cShift = 6; cOff = 0; }
    else if (t < 756)  { base = 252;  mtiles = 8;  Kpad = 832;  aOff = 1605632; bOff = 25088000; cShift = 7; cOff = 64; }
    else if (t < 1764) { base = 756;  mtiles = 16; Kpad = 256;  aOff = 2457600; bOff = 31744000; cShift = 8; cOff = 192; }
    else               { base = 1764; mtiles = 32; Kpad = 64;   aOff = 2981888; bOff = 33792000; cShift = 9; cOff = 448; }
    const int local = t - base;
    const int bm = (local % mtiles) * 128;
    const int bn = (local / mtiles) * 128;

    const __half* __restrict__ A = g_a + aOff;
    const __half* __restrict__ B = g_b + bOff;

    const int nkt = Kpad >> 6;

    auto load_stage = [&](int kt, int buf) {
        const uint32_t s = sb + buf * STAGE_BYTES;
        const int k0 = kt << 6;
#pragma unroll
        for (int q = 0; q < 4; q++) {
            int cid = q * 256 + tid;
            int ar = cid >> 3, ac = cid & 7;
            cp16(swzA(s + A_OFF, ar, ac), A + (size_t)(bm + ar) * Kpad + k0 + ac * 8, true);
            int br = cid >> 4, bc = cid & 15;
            int n = bn + bc * 8;
            cp16(swzB(s + B_OFF, br, bc), B + (size_t)(k0 + br) * NV + n, n < NV);
        }
    };

    float acc[2][8][4];
#pragma unroll
    for (int i = 0; i < 2; i++)
#pragma unroll
        for (int j = 0; j < 8; j++)
#pragma unroll
            for (int q = 0; q < 4; q++) acc[i][j][q] = 0.0f;

    load_stage(0, 0); CP_COMMIT();
    if (nkt > 1) load_stage(1, 1);
    CP_COMMIT();

    const int mid = lane >> 3, r8 = lane & 7;
    int buf = 0;

    for (int kt = 0; kt < nkt; kt++) {
        CP_WAIT1();
        __syncthreads();
        if (kt + 2 < nkt) {
            int nb = buf + 2; if (nb >= 3) nb -= 3;
            load_stage(kt + 2, nb);
        }
        CP_COMMIT();

        const uint32_t s = sb + buf * STAGE_BYTES;
#pragma unroll
        for (int ks = 0; ks < 4; ks++) {
            uint32_t ah[2][4], bh[4][4];
            int arow = wm * 32 + (mid & 1) * 8 + r8;
            int ach = ks * 2 + (mid >> 1);
#pragma unroll
            for (int mi = 0; mi < 2; mi++)
                LDSM4(ah[mi][0], ah[mi][1], ah[mi][2], ah[mi][3],
                      swzA(s + A_OFF, arow + mi * 16, ach));
            int brow = ks * 16 + (mid & 1) * 8 + r8;
#pragma unroll
            for (int nj = 0; nj < 4; nj++) {
                int bch = wn * 8 + nj * 2 + (mid >> 1);
                LDSM4T(bh[nj][0], bh[nj][1], bh[nj][2], bh[nj][3],
                       swzB(s + B_OFF, brow, bch));
            }
#pragma unroll
            for (int mi = 0; mi < 2; mi++) {
#pragma unroll
                for (int ni = 0; ni < 8; ni++) {
                    uint32_t* bp = &bh[ni >> 1][(ni & 1) * 2];
                    MMA(acc[mi][ni], ah[mi], bp[0], bp[1]);
                }
            }
        }
        buf++; if (buf == 3) buf = 0;
    }

    const int tg = lane >> 2, tq = lane & 3;
    const int Cm1 = (1 << cShift) - 1;
#pragma unroll
    for (int mi = 0; mi < 2; mi++) {
#pragma unroll
        for (int h = 0; h < 2; h++) {
            int m = bm + wm * 32 + mi * 16 + h * 8 + tg;
            int bI = m >> cShift;
            int c = m & Cm1;
            float* orow = out + ((size_t)bI * C_TOTAL + cOff + c) * NV;
            const float* wrow = g_wsel + (size_t)(cOff + c) * NV;
#pragma unroll
            for (int ni = 0; ni < 8; ni++) {
                int col = bn + wn * 64 + ni * 8 + tq * 2;
                if (col < NV) {
                    float2 wv = *(const float2*)(wrow + col);
                    float2 o;
                    o.x = acc[mi][ni][h * 2 + 0] * wv.x;
                    o.y = acc[mi][ni][h * 2 + 1] * wv.y;
                    *(float2*)(orow + col) = o;
                }
            }
        }
    }
}

// ---------------- launch ----------------
extern "C" void kernel_launch(void* const* d_in, const int* in_sizes, int n_in,
                              void* d_out, int out_size) {
    static const int fsz[4] = {1605632, 802816, 401408, 200704};
    static const int rsz[4] = {62720000, 15680000, 3920000, 980000};
    static const int wsz[4] = {1280000, 2560000, 5120000, 10240000};

    const float* fmap[4] = {0, 0, 0, 0};
    const float* rfp[4]  = {0, 0, 0, 0};
    const float* wptr[4] = {0, 0, 0, 0};
    const int*   roi = 0;

    for (int i = 0; i < n_in; i++) {
        int s = in_sizes[i];
        if (s == NV) { roi = (const int*)d_in[i]; continue; }
        for (int l = 0; l < 4; l++) {
            if (s == fsz[l]) fmap[l] = (const float*)d_in[i];
            else if (s == rsz[l]) rfp[l]  = (const float*)d_in[i];
            else if (s == wsz[l]) wptr[l] = (const float*)d_in[i];
        }
    }

    float* out = (float*)d_out;

    cudaFuncSetAttribute(mega, cudaFuncAttributeMaxDynamicSharedMemorySize, SMEM_TOTAL);

    zero_ctr<<<1, 1>>>();                                                      // 1
    mega<<<GRID_TOTAL, 256, SMEM_TOTAL>>>(out,
        rfp[0], rfp[1], rfp[2], rfp[3],
        fmap[0], fmap[1], fmap[2], fmap[3],
        wptr[0], wptr[1], wptr[2], wptr[3], roi);                              // 2
}

// round 17
// speedup vs baseline: 1.4282x; 1.4282x over previous
#include <cuda_runtime.h>
#include <cuda_fp16.h>
#include <cstdint>

#define NV 8000
#define NVT 20000
#define C_TOTAL 960
// Kpad multiples of 64: {3136, 832, 256, 64}
#define KPAD_SUM 4288
#define A_ELEMS 3244032   // 512*3136 + 1024*832 + 2048*256 + 4096*64

// ---------------- scratch (__device__ globals; allocation-free rule) ----------------
__device__ __align__(16) __half g_a[A_ELEMS];                    // fp16 fmap [M, Kpad]
__device__ __align__(16) __half g_b[(size_t)KPAD_SUM * NV];      // [Kpad, 8000] v-major fp16
__device__ __align__(16) float g_wsel[(size_t)C_TOTAL * NV];

// ---------------- roi dtype detect (int64 vs int32; values < 20000) ----------------
__device__ __forceinline__ bool roi_is64(const int* __restrict__ r32) {
    int acc = 0;
#pragma unroll
    for (int i = 1; i < 32; i += 2) acc |= r32[i];
    return acc == 0;
}

// ---------------- prep kernel (per segment; own lightweight launch config) ----------
// seg 0 = layer 0:   gather_b 12544 | split 1568 | gather_w 500   -> 14612 blocks
// seg 1 = layers123: gather_b  4608 | split 1600 | gather_w 7000  -> 13208 blocks
#define KPG 8
#define PA_BLOCKS 14612
#define PB_BLOCKS 13208

__device__ void role_gather_b(const float* rf, int K, int kp0, size_t bOff,
                              int vb, int tid, const int* __restrict__ roi) {
    const int v = vb * 256 + tid;
    if (v < NV) {
        const bool is64 = roi_is64(roi);
        const int ri = is64 ? roi[2 * v] : roi[v];
        const float* col = rf + ri;
        float x[KPG];
#pragma unroll
        for (int i = 0; i < KPG; i++) {
            int kp = kp0 + i;
            x[i] = (kp < K) ? __ldg(col + (size_t)kp * NVT) : 0.0f;
        }
#pragma unroll
        for (int i = 0; i < KPG; i++) {
            float a = x[i];
            a = (a > 0.0f) ? a : 0.01f * a;
            g_b[bOff + (size_t)(kp0 + i) * NV + v] = __float2half_rn(a);
        }
    }
}

__device__ void role_split(int idx0, const float* __restrict__ f0, const float* __restrict__ f1,
                           const float* __restrict__ f2, const float* __restrict__ f3) {
#pragma unroll
    for (int e = 0; e < 4; e++) {
        int idx = idx0 + e;
        const float* f; int K, Kpad, base;
        if (idx < 1605632)      { f = f0; K = 3136; Kpad = 3136; base = 0; }
        else if (idx < 2457600) { f = f1; K = 784;  Kpad = 832;  base = 1605632; }
        else if (idx < 2981888) { f = f2; K = 196;  Kpad = 256;  base = 2457600; }
        else                    { f = f3; K = 49;   Kpad = 64;   base = 2981888; }
        int local = idx - base;
        int m = local / Kpad, k = local - m * Kpad;
        float x = (k < K) ? f[(size_t)m * K + k] : 0.0f;
        g_a[idx] = __float2half_rn(x);
    }
}

__device__ void role_gather_w(long long idx0, const float* __restrict__ w0,
                              const float* __restrict__ w1, const float* __restrict__ w2,
                              const float* __restrict__ w3, const int* __restrict__ roi) {
    const bool is64 = roi_is64(roi);
#pragma unroll
    for (int e = 0; e < 4; e++) {
        long long idx = idx0 + e;
        int v = (int)(idx % NV);
        int c = (int)(idx / NV);
        const float* w; int lc;
        if (c < 64)       { w = w0; lc = c; }
        else if (c < 192) { w = w1; lc = c - 64; }
        else if (c < 448) { w = w2; lc = c - 192; }
        else              { w = w3; lc = c - 448; }
        int ri = is64 ? roi[2 * v] : roi[v];
        g_wsel[(size_t)c * NV + v] = w[(size_t)lc * NVT + (size_t)ri];
    }
}

__global__ void prep_seg(int seg,
                         const float* __restrict__ r0, const float* __restrict__ r1,
                         const float* __restrict__ r2, const float* __restrict__ r3,
                         const float* __restrict__ f0, const float* __restrict__ f1,
                         const float* __restrict__ f2, const float* __restrict__ f3,
                         const float* __restrict__ w0, const float* __restrict__ w1,
                         const float* __restrict__ w2, const float* __restrict__ w3,
                         const int* __restrict__ roi) {
    const int bid = blockIdx.x;
    const int tid = threadIdx.x;
    if (seg == 0) {
        if (bid < 12544) {
            int g = bid >> 5;
            role_gather_b(r0, 3136, g * KPG, 0, bid & 31, tid, roi);
        } else if (bid < 12544 + 1568) {
            role_split((bid - 12544) * 1024 + tid * 4, f0, f1, f2, f3);
        } else {
            role_gather_w((long long)(bid - 12544 - 1568) * 1024 + tid * 4,
                          w0, w1, w2, w3, roi);
        }
    } else {
        if (bid < 4608) {
            int g = bid >> 5;
            const float* rf; int K, kp0; size_t bOff;
            if (g < 104)      { rf = r1; K = 784; bOff = 25088000; kp0 = g * KPG; }
            else if (g < 136) { rf = r2; K = 196; bOff = 31744000; kp0 = (g - 104) * KPG; }
            else              { rf = r3; K = 49;  bOff = 33792000; kp0 = (g - 136) * KPG; }
            role_gather_b(rf, K, kp0, bOff, bid & 31, tid, roi);
        } else if (bid < 4608 + 1600) {
            role_split(1605632 + (bid - 4608) * 1024 + tid * 4, f0, f1, f2, f3);
        } else {
            role_gather_w(512000LL + (long long)(bid - 4608 - 1600) * 1024 + tid * 4,
                          w0, w1, w2, w3, roi);
        }
    }
}

// ---------------- fused fp16 mma.sync GEMM (R12/R15 config), tile-range param ----------
#define STAGE_BYTES 32768
#define A_OFF 0          // 128 rows x 128B
#define B_OFF 16384      // 64 rows x 256B
#define SMEM_TOTAL (3 * STAGE_BYTES)   // 96 KB

__device__ __forceinline__ uint32_t smem_u32(const void* p) {
    uint32_t a;
    asm("{ .reg .u64 t; cvta.to.shared.u64 t, %1; cvt.u32.u64 %0, t; }" : "=r"(a) : "l"(p));
    return a;
}
__device__ __forceinline__ uint32_t swzA(uint32_t base, int row, int chunk) {
    return base + (uint32_t)(row * 128 + (chunk ^ (row & 7)) * 16);
}
__device__ __forceinline__ uint32_t swzB(uint32_t base, int row, int chunk) {
    return base + (uint32_t)(row * 256 + (chunk ^ (row & 7)) * 16);
}
__device__ __forceinline__ void cp16(uint32_t dst, const void* src, bool v) {
    asm volatile("cp.async.cg.shared.global [%0], [%1], 16, %2;"
                 :: "r"(dst), "l"(src), "r"(v ? 16 : 0));
}
#define CP_COMMIT() asm volatile("cp.async.commit_group;" ::: "memory")
#define CP_WAIT1()  asm volatile("cp.async.wait_group 1;" ::: "memory")

#define LDSM4(r0, r1, r2, r3, a) \
    asm volatile("ldmatrix.sync.aligned.m8n8.x4.shared.b16 {%0,%1,%2,%3}, [%4];" \
                 : "=r"(r0), "=r"(r1), "=r"(r2), "=r"(r3) : "r"(a))
#define LDSM4T(r0, r1, r2, r3, a) \
    asm volatile("ldmatrix.sync.aligned.m8n8.x4.trans.shared.b16 {%0,%1,%2,%3}, [%4];" \
                 : "=r"(r0), "=r"(r1), "=r"(r2), "=r"(r3) : "r"(a))

#define MMA(d, a, b0_, b1_) \
    asm volatile("mma.sync.aligned.m16n8k16.row.col.f32.f16.f16.f32 " \
                 "{%0,%1,%2,%3}, {%4,%5,%6,%7}, {%8,%9}, {%0,%1,%2,%3};" \
                 : "+f"((d)[0]), "+f"((d)[1]), "+f"((d)[2]), "+f"((d)[3]) \
                 : "r"((a)[0]), "r"((a)[1]), "r"((a)[2]), "r"((a)[3]), "r"(b0_), "r"(b1_))

__global__ void __launch_bounds__(256, 2)
gemm_part(float* __restrict__ out, int tbase)
{
    extern __shared__ char smem[];
    const uint32_t sb = smem_u32(smem);
    const int tid = threadIdx.x;
    const int lane = tid & 31;
    const int w = tid >> 5;
    const int wm = w >> 1;          // 0..3 (m)
    const int wn = w & 1;           // 0..1 (n)

    const int t = tbase + blockIdx.x;
    int Kpad, cShift, cOff, mtiles, base; size_t aOff, bOff;
    if (t < 252)       { base = 0;    mtiles = 4;  Kpad = 3136; aOff = 0;       bOff = 0;        cShift = 6; cOff = 0; }
    else if (t < 756)  { base = 252;  mtiles = 8;  Kpad = 832;  aOff = 1605632; bOff = 25088000; cShift = 7; cOff = 64; }
    else if (t < 1764) { base = 756;  mtiles = 16; Kpad = 256;  aOff = 2457600; bOff = 31744000; cShift = 8; cOff = 192; }
    else               { base = 1764; mtiles = 32; Kpad = 64;   aOff = 2981888; bOff = 33792000; cShift = 9; cOff = 448; }
    const int local = t - base;
    const int bm = (local % mtiles) * 128;
    const int bn = (local / mtiles) * 128;

    const __half* __restrict__ A = g_a + aOff;
    const __half* __restrict__ B = g_b + bOff;

    const int nkt = Kpad >> 6;

    auto load_stage = [&](int kt, int buf) {
        const uint32_t s = sb + buf * STAGE_BYTES;
        const int k0 = kt << 6;
#pragma unroll
        for (int q = 0; q < 4; q++) {
            int cid = q * 256 + tid;
            int ar = cid >> 3, ac = cid & 7;
            cp16(swzA(s + A_OFF, ar, ac), A + (size_t)(bm + ar) * Kpad + k0 + ac * 8, true);
            int br = cid >> 4, bc = cid & 15;
            int n = bn + bc * 8;
            cp16(swzB(s + B_OFF, br, bc), B + (size_t)(k0 + br) * NV + n, n < NV);
        }
    };

    float acc[2][8][4];
#pragma unroll
    for (int i = 0; i < 2; i++)
#pragma unroll
        for (int j = 0; j < 8; j++)
#pragma unroll
            for (int q = 0; q < 4; q++) acc[i][j][q] = 0.0f;

    load_stage(0, 0); CP_COMMIT();
    if (nkt > 1) load_stage(1, 1);
    CP_COMMIT();

    const int mid = lane >> 3, r8 = lane & 7;
    int buf = 0;

    for (int kt = 0; kt < nkt; kt++) {
        CP_WAIT1();
        __syncthreads();
        if (kt + 2 < nkt) {
            int nb = buf + 2; if (nb >= 3) nb -= 3;
            load_stage(kt + 2, nb);
        }
        CP_COMMIT();

        const uint32_t s = sb + buf * STAGE_BYTES;
#pragma unroll
        for (int ks = 0; ks < 4; ks++) {
            uint32_t ah[2][4], bh[4][4];
            int arow = wm * 32 + (mid & 1) * 8 + r8;
            int ach = ks * 2 + (mid >> 1);
#pragma unroll
            for (int mi = 0; mi < 2; mi++)
                LDSM4(ah[mi][0], ah[mi][1], ah[mi][2], ah[mi][3],
                      swzA(s + A_OFF, arow + mi * 16, ach));
            int brow = ks * 16 + (mid & 1) * 8 + r8;
#pragma unroll
            for (int nj = 0; nj < 4; nj++) {
                int bch = wn * 8 + nj * 2 + (mid >> 1);
                LDSM4T(bh[nj][0], bh[nj][1], bh[nj][2], bh[nj][3],
                       swzB(s + B_OFF, brow, bch));
            }
#pragma unroll
            for (int mi = 0; mi < 2; mi++) {
#pragma unroll
                for (int ni = 0; ni < 8; ni++) {
                    uint32_t* bp = &bh[ni >> 1][(ni & 1) * 2];
                    MMA(acc[mi][ni], ah[mi], bp[0], bp[1]);
                }
            }
        }
        buf++; if (buf == 3) buf = 0;
    }

    const int tg = lane >> 2, tq = lane & 3;
    const int Cm1 = (1 << cShift) - 1;
#pragma unroll
    for (int mi = 0; mi < 2; mi++) {
#pragma unroll
        for (int h = 0; h < 2; h++) {
            int m = bm + wm * 32 + mi * 16 + h * 8 + tg;
            int bI = m >> cShift;
            int c = m & Cm1;
            float* orow = out + ((size_t)bI * C_TOTAL + cOff + c) * NV;
            const float* wrow = g_wsel + (size_t)(cOff + c) * NV;
#pragma unroll
            for (int ni = 0; ni < 8; ni++) {
                int col = bn + wn * 64 + ni * 8 + tq * 2;
                if (col < NV) {
                    float2 wv = *(const float2*)(wrow + col);
                    float2 o;
                    o.x = acc[mi][ni][h * 2 + 0] * wv.x;
                    o.y = acc[mi][ni][h * 2 + 1] * wv.y;
                    *(float2*)(orow + col) = o;
                }
            }
        }
    }
}

// ---------------- launch: two parallel chains via stream fork/join ----------------
extern "C" void kernel_launch(void* const* d_in, const int* in_sizes, int n_in,
                              void* d_out, int out_size) {
    static const int fsz[4] = {1605632, 802816, 401408, 200704};
    static const int rsz[4] = {62720000, 15680000, 3920000, 980000};
    static const int wsz[4] = {1280000, 2560000, 5120000, 10240000};

    const float* fmap[4] = {0, 0, 0, 0};
    const float* rfp[4]  = {0, 0, 0, 0};
    const float* wptr[4] = {0, 0, 0, 0};
    const int*   roi = 0;

    for (int i = 0; i < n_in; i++) {
        int s = in_sizes[i];
        if (s == NV) { roi = (const int*)d_in[i]; continue; }
        for (int l = 0; l < 4; l++) {
            if (s == fsz[l]) fmap[l] = (const float*)d_in[i];
            else if (s == rsz[l]) rfp[l]  = (const float*)d_in[i];
            else if (s == wsz[l]) wptr[l] = (const float*)d_in[i];
        }
    }

    float* out = (float*)d_out;

    cudaFuncSetAttribute(gemm_part, cudaFuncAttributeMaxDynamicSharedMemorySize, SMEM_TOTAL);

    cudaStream_t s2;
    cudaStreamCreateWithFlags(&s2, cudaStreamNonBlocking);
    cudaEvent_t eFork, eJoin;
    cudaEventCreateWithFlags(&eFork, cudaEventDisableTiming);
    cudaEventCreateWithFlags(&eJoin, cudaEventDisableTiming);

    // fork: s2 joins the capture dependency chain
    cudaEventRecord(eFork, 0);
    cudaStreamWaitEvent(s2, eFork, 0);

    // chain A (default stream): layer-0 prep -> layer-0 GEMM
    prep_seg<<<PA_BLOCKS, 256>>>(0, rfp[0], rfp[1], rfp[2], rfp[3],
                                 fmap[0], fmap[1], fmap[2], fmap[3],
                                 wptr[0], wptr[1], wptr[2], wptr[3], roi);
    gemm_part<<<252, 256, SMEM_TOTAL>>>(out, 0);

    // chain B (s2): layers-1..3 prep -> layers-1..3 GEMM
    prep_seg<<<PB_BLOCKS, 256, 0, s2>>>(1, rfp[0], rfp[1], rfp[2], rfp[3],
                                        fmap[0], fmap[1], fmap[2], fmap[3],
                                        wptr[0], wptr[1], wptr[2], wptr[3], roi);
    gemm_part<<<3528, 256, SMEM_TOTAL, s2>>>(out, 252);

    // join: default stream waits for chain B
    cudaEventRecord(eJoin, s2);
    cudaStreamWaitEvent(0, eJoin, 0);

    cudaStreamDestroy(s2);
    cudaEventDestroy(eFork);
    cudaEventDestroy(eJoin);
}